// round 15
// baseline (speedup 1.0000x reference)
#include <cuda_runtime.h>
#include <cuda_bf16.h>
#include <cstddef>

#define B_ 32
#define T_ 512
#define H_ 1024
#define G_ 4096
#define NB 128

__device__ float g_gx[(size_t)B_ * T_ * G_];
__device__ float g_out0[(size_t)B_ * T_ * H_];
__device__ __nv_bfloat16 g_hb[2][2][(size_t)B_ * H_];
__device__ unsigned g_bars[8 * 32];                 // chunk-group flags, 128B apart
__device__ __nv_bfloat16 g_Ahi[(size_t)B_ * T_ * H_];
__device__ __nv_bfloat16 g_Alo[(size_t)B_ * T_ * H_];
__device__ __nv_bfloat16 g_Whi[(size_t)G_ * H_];
__device__ __nv_bfloat16 g_Wlo[(size_t)G_ * H_];

__global__ __launch_bounds__(256) void conv_split(
    const float* __restrict__ s, __nv_bfloat16* __restrict__ hi,
    __nv_bfloat16* __restrict__ lo, int n4)
{
    int i = blockIdx.x * 256 + threadIdx.x;
    if (i >= n4) return;
    float4 v = ((const float4*)s)[i];
    __nv_bfloat16 h0 = __float2bfloat16(v.x), h1 = __float2bfloat16(v.y);
    __nv_bfloat16 h2 = __float2bfloat16(v.z), h3 = __float2bfloat16(v.w);
    __nv_bfloat16 l0 = __float2bfloat16(v.x - __bfloat162float(h0));
    __nv_bfloat16 l1 = __float2bfloat16(v.y - __bfloat162float(h1));
    __nv_bfloat16 l2 = __float2bfloat16(v.z - __bfloat162float(h2));
    __nv_bfloat16 l3 = __float2bfloat16(v.w - __bfloat162float(h3));
    ((__nv_bfloat162*)hi)[i * 2]     = __nv_bfloat162(h0, h1);
    ((__nv_bfloat162*)hi)[i * 2 + 1] = __nv_bfloat162(h2, h3);
    ((__nv_bfloat162*)lo)[i * 2]     = __nv_bfloat162(l0, l1);
    ((__nv_bfloat162*)lo)[i * 2 + 1] = __nv_bfloat162(l2, l3);
}

__device__ __forceinline__ void ldsm4(unsigned* r, unsigned a) {
    asm volatile("ldmatrix.sync.aligned.m8n8.x4.shared.b16 {%0,%1,%2,%3}, [%4];"
                 : "=r"(r[0]), "=r"(r[1]), "=r"(r[2]), "=r"(r[3]) : "r"(a));
}
__device__ __forceinline__ void mma16816(float* c, const unsigned* a,
                                         unsigned b0, unsigned b1) {
    asm volatile(
        "mma.sync.aligned.m16n8k16.row.col.f32.bf16.bf16.f32 "
        "{%0,%1,%2,%3}, {%4,%5,%6,%7}, {%8,%9}, {%0,%1,%2,%3};"
        : "+f"(c[0]), "+f"(c[1]), "+f"(c[2]), "+f"(c[3])
        : "r"(a[0]), "r"(a[1]), "r"(a[2]), "r"(a[3]), "r"(b0), "r"(b1));
}
__device__ __forceinline__ void cpa(unsigned s, const void* g) {
    asm volatile("cp.async.cg.shared.global [%0], [%1], 16;" :: "r"(s), "l"(g));
}

// ---------------- tensor-core GEMM (unchanged) --------------------------------
#define SR 40
#define BUFB (128 * SR * 2)
#define OFF_AH 0
#define OFF_AL (2 * BUFB)
#define OFF_BH (4 * BUFB)
#define OFF_BL (6 * BUFB)
#define TC_SMEM (8 * BUFB)

__global__ __launch_bounds__(256, 1) void tc_gemm(
    const __nv_bfloat16* __restrict__ Ahi, const __nv_bfloat16* __restrict__ Alo,
    const __nv_bfloat16* __restrict__ Whi, const __nv_bfloat16* __restrict__ Wlo,
    const float* __restrict__ bias)
{
    extern __shared__ char sm[];
    const unsigned sbase = (unsigned)__cvta_generic_to_shared(sm);
    const int tid = threadIdx.x, lane = tid & 31, wid = tid >> 5;
    const int wm = wid & 3, wn = wid >> 2;
    const int m0 = blockIdx.y * 128, n0 = blockIdx.x * 128;

    int frow[2], fch[2];
    unsigned sA[2];
#pragma unroll
    for (int u = 0; u < 2; ++u) {
        int id = tid + 256 * u;
        frow[u] = id >> 2; fch[u] = (id & 3) * 8;
        sA[u] = (frow[u] * SR + fch[u]) * 2;
    }
    const int arow = wm * 32 + (lane & 7) + (lane & 8);
    const unsigned a_base = (arow * SR + (lane >> 4) * 8) * 2;
    const int brow = wn * 64 + (lane & 7) + (lane >> 4) * 8;
    const unsigned b_base = (brow * SR + ((lane >> 3) & 1) * 8) * 2;

    float c[2][8][4];
#pragma unroll
    for (int i = 0; i < 2; ++i)
#pragma unroll
        for (int j = 0; j < 8; ++j)
#pragma unroll
            for (int q = 0; q < 4; ++q) c[i][j][q] = 0.f;

#pragma unroll
    for (int u = 0; u < 2; ++u) {
        size_t ga = (size_t)(m0 + frow[u]) * H_ + fch[u];
        size_t gb = (size_t)(n0 + frow[u]) * H_ + fch[u];
        cpa(sbase + OFF_AH + sA[u], &Ahi[ga]);
        cpa(sbase + OFF_AL + sA[u], &Alo[ga]);
        cpa(sbase + OFF_BH + sA[u], &Whi[gb]);
        cpa(sbase + OFF_BL + sA[u], &Wlo[gb]);
    }
    asm volatile("cp.async.commit_group;");

    for (int s = 0; s < 32; ++s) {
        asm volatile("cp.async.wait_group 0;");
        __syncthreads();
        if (s + 1 < 32) {
            int k0 = (s + 1) * 32, bf = (s + 1) & 1;
#pragma unroll
            for (int u = 0; u < 2; ++u) {
                size_t ga = (size_t)(m0 + frow[u]) * H_ + k0 + fch[u];
                size_t gb = (size_t)(n0 + frow[u]) * H_ + k0 + fch[u];
                cpa(sbase + OFF_AH + bf * BUFB + sA[u], &Ahi[ga]);
                cpa(sbase + OFF_AL + bf * BUFB + sA[u], &Alo[ga]);
                cpa(sbase + OFF_BH + bf * BUFB + sA[u], &Whi[gb]);
                cpa(sbase + OFF_BL + bf * BUFB + sA[u], &Wlo[gb]);
            }
            asm volatile("cp.async.commit_group;");
        }
        const unsigned bo = (s & 1) * BUFB;
#pragma unroll
        for (int kk = 0; kk < 2; ++kk) {
            unsigned ah[2][4], al[2][4], bh[4][4], bl[4][4];
#pragma unroll
            for (int mi = 0; mi < 2; ++mi) {
                unsigned ad = sbase + bo + a_base + mi * (16 * SR * 2) + kk * 32;
                ldsm4(ah[mi], ad + OFF_AH);
                ldsm4(al[mi], ad + OFF_AL);
            }
#pragma unroll
            for (int j = 0; j < 4; ++j) {
                unsigned bd = sbase + bo + b_base + j * (16 * SR * 2) + kk * 32;
                ldsm4(bh[j], bd + OFF_BH);
                ldsm4(bl[j], bd + OFF_BL);
            }
#pragma unroll
            for (int mi = 0; mi < 2; ++mi)
#pragma unroll
                for (int j = 0; j < 4; ++j) {
                    mma16816(c[mi][2*j],   ah[mi], bh[j][0], bh[j][1]);
                    mma16816(c[mi][2*j+1], ah[mi], bh[j][2], bh[j][3]);
                    mma16816(c[mi][2*j],   ah[mi], bl[j][0], bl[j][1]);
                    mma16816(c[mi][2*j+1], ah[mi], bl[j][2], bl[j][3]);
                    mma16816(c[mi][2*j],   al[mi], bh[j][0], bh[j][1]);
                    mma16816(c[mi][2*j+1], al[mi], bh[j][2], bh[j][3]);
                }
        }
        __syncthreads();
    }
#pragma unroll
    for (int mi = 0; mi < 2; ++mi) {
        int gr = m0 + wm * 32 + mi * 16 + (lane >> 2);
#pragma unroll
        for (int ni = 0; ni < 8; ++ni) {
            int gc = n0 + wn * 64 + ni * 8 + (lane & 3) * 2;
            float2 bv = *(const float2*)&bias[gc];
            float* cc = c[mi][ni];
            *(float2*)&g_gx[(size_t)gr * G_ + gc] =
                make_float2(cc[0] + bv.x, cc[1] + bv.y);
            *(float2*)&g_gx[(size_t)(gr + 8) * G_ + gc] =
                make_float2(cc[2] + bv.x, cc[3] + bv.y);
        }
    }
}

// ---------------- persistent LSTM recurrence: cheap-poll dataflow -------------
__device__ __forceinline__ float sigf(float x) { return 1.0f / (1.0f + __expf(-x)); }

__device__ __forceinline__ void pollge(const unsigned* p, unsigned want) {
    unsigned v;
    do {
        asm volatile("ld.acquire.gpu.global.u32 %0, [%1];" : "=r"(v) : "l"(p));
    } while (v < want);
}
__device__ __forceinline__ void rel_inc(unsigned* p) {
    asm volatile("red.release.gpu.global.add.u32 [%0], 1;" :: "l"(p) : "memory");
}

// SMEM byte offsets (R13 layout)
#define WSTR 1032
#define OFF_WHI 0
#define OFF_WLO (32 * WSTR * 2)
#define OFF_HS  (2 * 32 * WSTR * 2)
#define HSTR 136
#define HS_HILO (32 * HSTR * 2)
#define HS_BUF  (2 * HS_HILO)
#define OFF_RED (OFF_HS + 2 * HS_BUF)
#define OFF_GS  (OFF_RED + 16 * 32 * 16 * 4)
#define OFF_LEN (OFF_GS + 32 * 36 * 4)
#define REC_SMEM (OFF_LEN + 128)

__global__ __launch_bounds__(512, 1) void lstm_rec(
    const float* __restrict__ whh, const void* __restrict__ len_raw,
    float* __restrict__ outp, float* __restrict__ cdst, float* __restrict__ hdst)
{
    extern __shared__ char sm[];
    const unsigned sbase = (unsigned)__cvta_generic_to_shared(sm);
    float* red = (float*)(sm + OFF_RED);
    float* g_s = (float*)(sm + OFF_GS);
    int* len_s = (int*)(sm + OFF_LEN);

    const int tid = threadIdx.x, lane = tid & 31, wid = tid >> 5;
    const int bid = blockIdx.x;
    const int j0 = bid * 8;
    const int grp = bid >> 4;                  // this CTA's h-chunk group

    if (tid == 0) {
        const int* L = (const int*)len_raw;
        bool is64 = true;
        for (int i = 1; i < 32; i += 2) if (L[i] != 0) { is64 = false; break; }
        for (int b = 0; b < 32; ++b) len_s[b] = is64 ? L[2 * b] : L[b];
    }

    // stage + split W_hh slice
    {
        const int r = tid & 31;
        const int grow = (r >> 3) * 1024 + j0 + (r & 7);
        const int k0 = (tid >> 5) * 64;
        const float* src = &whh[(size_t)grow * H_ + k0];
        __nv_bfloat162* whi = (__nv_bfloat162*)(sm + OFF_WHI);
        __nv_bfloat162* wlo = (__nv_bfloat162*)(sm + OFF_WLO);
#pragma unroll
        for (int kk = 0; kk < 64; kk += 4) {
            float4 v = *(const float4*)&src[kk];
            __nv_bfloat16 h0 = __float2bfloat16(v.x), h1 = __float2bfloat16(v.y);
            __nv_bfloat16 h2 = __float2bfloat16(v.z), h3 = __float2bfloat16(v.w);
            int e = r * WSTR + k0 + kk;
            whi[e / 2]     = __nv_bfloat162(h0, h1);
            whi[e / 2 + 1] = __nv_bfloat162(h2, h3);
            wlo[e / 2]     = __nv_bfloat162(__float2bfloat16(v.x - __bfloat162float(h0)),
                                            __float2bfloat16(v.y - __bfloat162float(h1)));
            wlo[e / 2 + 1] = __nv_bfloat162(__float2bfloat16(v.z - __bfloat162float(h2)),
                                            __float2bfloat16(v.w - __bfloat162float(h3)));
        }
    }

    const int kw = wid >> 1, nh = wid & 1;
    const unsigned a_off = ((lane & 7) + (lane & 8)) * (WSTR * 2) + ((lane >> 4) * 8) * 2;
    const unsigned b_off = ((nh * 16 + (lane & 7) + (lane >> 4) * 8) * HSTR
                            + ((lane >> 3) & 1) * 8) * 2;

    const int shl = tid >> 8, srem = tid & 255;
    const int sb = srem >> 3, sk = (srem & 7) * 16;
    const unsigned s_dst = OFF_HS + shl * HS_HILO + (sb * HSTR + sk) * 2;

    const int rm = tid >> 4, rn2 = (tid & 15) * 2;
    const int rslot_nh = rn2 >> 4, rcol = rn2 & 15;
    const size_t ocol = (size_t)(rm >> 3) * 1024 + j0 + (rm & 7);

    const int ju = tid & 7, bu = tid >> 3;
    float c_reg = 0.f, h_reg = 0.f;
    if (tid < 256) {
        g_hb[0][0][bu * H_ + j0 + ju] = __float2bfloat16(0.f);
        g_hb[0][1][bu * H_ + j0 + ju] = __float2bfloat16(0.f);
    }
    __syncthreads();
    if (tid == 0) rel_inc(&g_bars[grp * 32]);   // publish h(0)

    for (int t = 0; t < T_; ++t) {
        const unsigned want = 16u * (t + 1);
        float gx0 = __ldg(&g_gx[((size_t)rn2 * T_ + t) * G_ + ocol]);
        float gx1 = __ldg(&g_gx[((size_t)(rn2 + 1) * T_ + t) * G_ + ocol]);

        const __nv_bfloat16* hsrc = g_hb[t & 1][shl];

        // verify flags 0,1 (one thread each), then all may LDG chunks 0,1
        if (tid < 2) pollge(&g_bars[tid * 32], want);
        __syncthreads();

        // stage chunk 0
        uint4 nxt0 = __ldcg((const uint4*)&hsrc[(size_t)sb * H_ + sk]);
        uint4 nxt1 = __ldcg((const uint4*)&hsrc[(size_t)sb * H_ + sk] + 1);
        *(uint4*)(sm + s_dst)      = nxt0;
        *(uint4*)(sm + s_dst + 16) = nxt1;
        __syncthreads();

        float c[2][2][4];
#pragma unroll
        for (int mi = 0; mi < 2; ++mi)
#pragma unroll
            for (int nj = 0; nj < 2; ++nj)
#pragma unroll
                for (int q = 0; q < 4; ++q) c[mi][nj][q] = 0.f;

        for (int kc = 0; kc < 8; ++kc) {
            if (kc < 7) {
                // flag[kc+1] verified during iter kc-1 (or prologue)
                nxt0 = __ldcg((const uint4*)&hsrc[(size_t)sb * H_ + (kc + 1) * 128 + sk]);
                nxt1 = __ldcg((const uint4*)&hsrc[(size_t)sb * H_ + (kc + 1) * 128 + sk] + 1);
            }
            // one lane (in warp kc+2) verifies flag[kc+2]; end-of-iter sync enforces
            if (kc < 6 && tid == (kc + 2) * 32)
                pollge(&g_bars[(kc + 2) * 32], want);
            const unsigned hb_s = sbase + OFF_HS + (kc & 1) * HS_BUF;
            {
                const int kloc = kw * 16;
                const int kg = kc * 128 + kloc;
                unsigned ah[2][4], al[2][4], bh[4], bl[4];
                unsigned bd = hb_s + b_off + kloc * 2;
                ldsm4(bh, bd);
                ldsm4(bl, bd + HS_HILO);
#pragma unroll
                for (int mi = 0; mi < 2; ++mi) {
                    unsigned ad = sbase + a_off + (mi * 16 * WSTR + kg) * 2;
                    ldsm4(ah[mi], ad + OFF_WHI);
                    ldsm4(al[mi], ad + OFF_WLO);
                }
#pragma unroll
                for (int mi = 0; mi < 2; ++mi)
#pragma unroll
                    for (int nj = 0; nj < 2; ++nj) {
                        mma16816(c[mi][nj], ah[mi], bh[2*nj], bh[2*nj+1]);
                        mma16816(c[mi][nj], ah[mi], bl[2*nj], bl[2*nj+1]);
                        mma16816(c[mi][nj], al[mi], bh[2*nj], bh[2*nj+1]);
                    }
            }
            if (kc < 7) {
                const unsigned nb_s = s_dst + ((kc + 1) & 1) * HS_BUF;
                *(uint4*)(sm + nb_s)      = nxt0;
                *(uint4*)(sm + nb_s + 16) = nxt1;
            }
            __syncthreads();
        }

#pragma unroll
        for (int mi = 0; mi < 2; ++mi)
#pragma unroll
            for (int nj = 0; nj < 2; ++nj) {
                int m = mi * 16 + (lane >> 2);
                int nl = nj * 8 + (lane & 3) * 2;
                float* rb = &red[((kw * 2 + nh) * 32) * 16];
                *(float2*)&rb[m * 16 + nl]       = make_float2(c[mi][nj][0], c[mi][nj][1]);
                *(float2*)&rb[(m + 8) * 16 + nl] = make_float2(c[mi][nj][2], c[mi][nj][3]);
            }
        __syncthreads();

        {
            float s0 = gx0, s1 = gx1;
#pragma unroll
            for (int s = 0; s < 8; ++s) {
                float2 p = *(float2*)&red[((s * 2 + rslot_nh) * 32 + rm) * 16 + rcol];
                s0 += p.x; s1 += p.y;
            }
            g_s[rm * 36 + rn2]     = s0;
            g_s[rm * 36 + rn2 + 1] = s1;
        }
        __syncthreads();

        if (tid < 256) {
            float fg = sigf(g_s[(0 * 8 + ju) * 36 + bu]);
            float ig = sigf(g_s[(1 * 8 + ju) * 36 + bu]);
            float og = sigf(g_s[(2 * 8 + ju) * 36 + bu]);
            float cg = tanhf(g_s[(3 * 8 + ju) * 36 + bu]);
            float cn = fg * c_reg + ig * cg;
            float hn = og * tanhf(cn);
            if (t < len_s[bu]) { c_reg = cn; h_reg = hn; }
            __nv_bfloat16 hh = __float2bfloat16(h_reg);
            __nv_bfloat16 hl = __float2bfloat16(h_reg - __bfloat162float(hh));
            int nbuf = (t & 1) ^ 1;
            g_hb[nbuf][0][bu * H_ + j0 + ju] = hh;
            g_hb[nbuf][1][bu * H_ + j0 + ju] = hl;
            outp[((size_t)bu * T_ + t) * H_ + (j0 + ju)] = h_reg;
        }
        __syncthreads();
        if (tid == 0) rel_inc(&g_bars[grp * 32]);   // publish h(t+1)
    }
    if (tid < 256) {
        cdst[(size_t)bu * H_ + j0 + ju] = c_reg;
        hdst[(size_t)bu * H_ + j0 + ju] = h_reg;
    }
}

extern "C" void kernel_launch(void* const* d_in, const int* in_sizes, int n_in,
                              void* d_out, int out_size)
{
    const float* x    = (const float*)d_in[0];
    const void*  len  = d_in[1];
    const float* wih0 = (const float*)d_in[2];
    const float* whh0 = (const float*)d_in[3];
    const float* b0   = (const float*)d_in[4];
    const float* wih1 = (const float*)d_in[5];
    const float* whh1 = (const float*)d_in[6];
    const float* b1   = (const float*)d_in[7];
    float* out = (float*)d_out;

    void *bar_p, *out0_p, *ahi_p, *alo_p, *whi_p, *wlo_p;
    cudaGetSymbolAddress(&bar_p, g_bars);
    cudaGetSymbolAddress(&out0_p, g_out0);
    cudaGetSymbolAddress(&ahi_p, g_Ahi);
    cudaGetSymbolAddress(&alo_p, g_Alo);
    cudaGetSymbolAddress(&whi_p, g_Whi);
    cudaGetSymbolAddress(&wlo_p, g_Wlo);
    float* out0 = (float*)out0_p;
    __nv_bfloat16* Ahi = (__nv_bfloat16*)ahi_p;
    __nv_bfloat16* Alo = (__nv_bfloat16*)alo_p;
    __nv_bfloat16* Whi = (__nv_bfloat16*)whi_p;
    __nv_bfloat16* Wlo = (__nv_bfloat16*)wlo_p;

    cudaFuncSetAttribute(lstm_rec, cudaFuncAttributeMaxDynamicSharedMemorySize, REC_SMEM);
    cudaFuncSetAttribute(tc_gemm, cudaFuncAttributeMaxDynamicSharedMemorySize, TC_SMEM);

    const size_t O1 = (size_t)B_ * T_ * H_;
    float* c0dst = out + O1;
    float* c1dst = out + O1 + (size_t)B_ * H_;
    float* h0dst = out + O1 + 2 * (size_t)B_ * H_;
    float* h1dst = out + O1 + 3 * (size_t)B_ * H_;

    const int nA4 = (B_ * T_ * H_) / 4;
    const int nW4 = (G_ * H_) / 4;
    dim3 gg(G_ / 128, (B_ * T_) / 128);

    conv_split<<<nW4 / 256, 256>>>(wih0, Whi, Wlo, nW4);
    conv_split<<<nA4 / 256, 256>>>(x, Ahi, Alo, nA4);
    tc_gemm<<<gg, 256, TC_SMEM>>>(Ahi, Alo, Whi, Wlo, b0);
    cudaMemsetAsync(bar_p, 0, 8 * 32 * sizeof(unsigned), 0);
    lstm_rec<<<NB, 512, REC_SMEM>>>(whh0, len, out0, c0dst, h0dst);

    conv_split<<<nW4 / 256, 256>>>(wih1, Whi, Wlo, nW4);
    conv_split<<<nA4 / 256, 256>>>(out0, Ahi, Alo, nA4);
    tc_gemm<<<gg, 256, TC_SMEM>>>(Ahi, Alo, Whi, Wlo, b1);
    cudaMemsetAsync(bar_p, 0, 8 * 32 * sizeof(unsigned), 0);
    lstm_rec<<<NB, 512, REC_SMEM>>>(whh1, len, out, c1dst, h1dst);
}

// round 16
// speedup vs baseline: 1.1076x; 1.1076x over previous
#include <cuda_runtime.h>
#include <cuda_bf16.h>
#include <cstddef>

#define B_ 32
#define T_ 512
#define H_ 1024
#define G_ 4096
#define NB 128

__device__ float g_gx[(size_t)B_ * T_ * G_];
__device__ float g_out0[(size_t)B_ * T_ * H_];
__device__ __nv_bfloat16 g_hb[2][2][(size_t)B_ * H_];
__device__ unsigned g_bars[8 * 32];
__device__ __nv_bfloat16 g_Ahi[(size_t)B_ * T_ * H_];
__device__ __nv_bfloat16 g_Alo[(size_t)B_ * T_ * H_];
__device__ __nv_bfloat16 g_Whi[(size_t)G_ * H_];
__device__ __nv_bfloat16 g_Wlo[(size_t)G_ * H_];

__global__ __launch_bounds__(256) void conv_split(
    const float* __restrict__ s, __nv_bfloat16* __restrict__ hi,
    __nv_bfloat16* __restrict__ lo, int n4)
{
    int i = blockIdx.x * 256 + threadIdx.x;
    if (i >= n4) return;
    float4 v = ((const float4*)s)[i];
    __nv_bfloat16 h0 = __float2bfloat16(v.x), h1 = __float2bfloat16(v.y);
    __nv_bfloat16 h2 = __float2bfloat16(v.z), h3 = __float2bfloat16(v.w);
    __nv_bfloat16 l0 = __float2bfloat16(v.x - __bfloat162float(h0));
    __nv_bfloat16 l1 = __float2bfloat16(v.y - __bfloat162float(h1));
    __nv_bfloat16 l2 = __float2bfloat16(v.z - __bfloat162float(h2));
    __nv_bfloat16 l3 = __float2bfloat16(v.w - __bfloat162float(h3));
    ((__nv_bfloat162*)hi)[i * 2]     = __nv_bfloat162(h0, h1);
    ((__nv_bfloat162*)hi)[i * 2 + 1] = __nv_bfloat162(h2, h3);
    ((__nv_bfloat162*)lo)[i * 2]     = __nv_bfloat162(l0, l1);
    ((__nv_bfloat162*)lo)[i * 2 + 1] = __nv_bfloat162(l2, l3);
}

__device__ __forceinline__ void ldsm4(unsigned* r, unsigned a) {
    asm volatile("ldmatrix.sync.aligned.m8n8.x4.shared.b16 {%0,%1,%2,%3}, [%4];"
                 : "=r"(r[0]), "=r"(r[1]), "=r"(r[2]), "=r"(r[3]) : "r"(a));
}
__device__ __forceinline__ void mma16816(float* c, const unsigned* a,
                                         unsigned b0, unsigned b1) {
    asm volatile(
        "mma.sync.aligned.m16n8k16.row.col.f32.bf16.bf16.f32 "
        "{%0,%1,%2,%3}, {%4,%5,%6,%7}, {%8,%9}, {%0,%1,%2,%3};"
        : "+f"(c[0]), "+f"(c[1]), "+f"(c[2]), "+f"(c[3])
        : "r"(a[0]), "r"(a[1]), "r"(a[2]), "r"(a[3]), "r"(b0), "r"(b1));
}
__device__ __forceinline__ void cpa(unsigned s, const void* g) {
    asm volatile("cp.async.cg.shared.global [%0], [%1], 16;" :: "r"(s), "l"(g));
}

// ---------------- tensor-core GEMM (unchanged) --------------------------------
#define SR 40
#define BUFB (128 * SR * 2)
#define OFF_AH 0
#define OFF_AL (2 * BUFB)
#define OFF_BH (4 * BUFB)
#define OFF_BL (6 * BUFB)
#define TC_SMEM (8 * BUFB)

__global__ __launch_bounds__(256, 1) void tc_gemm(
    const __nv_bfloat16* __restrict__ Ahi, const __nv_bfloat16* __restrict__ Alo,
    const __nv_bfloat16* __restrict__ Whi, const __nv_bfloat16* __restrict__ Wlo,
    const float* __restrict__ bias)
{
    extern __shared__ char sm[];
    const unsigned sbase = (unsigned)__cvta_generic_to_shared(sm);
    const int tid = threadIdx.x, lane = tid & 31, wid = tid >> 5;
    const int wm = wid & 3, wn = wid >> 2;
    const int m0 = blockIdx.y * 128, n0 = blockIdx.x * 128;

    int frow[2], fch[2];
    unsigned sA[2];
#pragma unroll
    for (int u = 0; u < 2; ++u) {
        int id = tid + 256 * u;
        frow[u] = id >> 2; fch[u] = (id & 3) * 8;
        sA[u] = (frow[u] * SR + fch[u]) * 2;
    }
    const int arow = wm * 32 + (lane & 7) + (lane & 8);
    const unsigned a_base = (arow * SR + (lane >> 4) * 8) * 2;
    const int brow = wn * 64 + (lane & 7) + (lane >> 4) * 8;
    const unsigned b_base = (brow * SR + ((lane >> 3) & 1) * 8) * 2;

    float c[2][8][4];
#pragma unroll
    for (int i = 0; i < 2; ++i)
#pragma unroll
        for (int j = 0; j < 8; ++j)
#pragma unroll
            for (int q = 0; q < 4; ++q) c[i][j][q] = 0.f;

#pragma unroll
    for (int u = 0; u < 2; ++u) {
        size_t ga = (size_t)(m0 + frow[u]) * H_ + fch[u];
        size_t gb = (size_t)(n0 + frow[u]) * H_ + fch[u];
        cpa(sbase + OFF_AH + sA[u], &Ahi[ga]);
        cpa(sbase + OFF_AL + sA[u], &Alo[ga]);
        cpa(sbase + OFF_BH + sA[u], &Whi[gb]);
        cpa(sbase + OFF_BL + sA[u], &Wlo[gb]);
    }
    asm volatile("cp.async.commit_group;");

    for (int s = 0; s < 32; ++s) {
        asm volatile("cp.async.wait_group 0;");
        __syncthreads();
        if (s + 1 < 32) {
            int k0 = (s + 1) * 32, bf = (s + 1) & 1;
#pragma unroll
            for (int u = 0; u < 2; ++u) {
                size_t ga = (size_t)(m0 + frow[u]) * H_ + k0 + fch[u];
                size_t gb = (size_t)(n0 + frow[u]) * H_ + k0 + fch[u];
                cpa(sbase + OFF_AH + bf * BUFB + sA[u], &Ahi[ga]);
                cpa(sbase + OFF_AL + bf * BUFB + sA[u], &Alo[ga]);
                cpa(sbase + OFF_BH + bf * BUFB + sA[u], &Whi[gb]);
                cpa(sbase + OFF_BL + bf * BUFB + sA[u], &Wlo[gb]);
            }
            asm volatile("cp.async.commit_group;");
        }
        const unsigned bo = (s & 1) * BUFB;
#pragma unroll
        for (int kk = 0; kk < 2; ++kk) {
            unsigned ah[2][4], al[2][4], bh[4][4], bl[4][4];
#pragma unroll
            for (int mi = 0; mi < 2; ++mi) {
                unsigned ad = sbase + bo + a_base + mi * (16 * SR * 2) + kk * 32;
                ldsm4(ah[mi], ad + OFF_AH);
                ldsm4(al[mi], ad + OFF_AL);
            }
#pragma unroll
            for (int j = 0; j < 4; ++j) {
                unsigned bd = sbase + bo + b_base + j * (16 * SR * 2) + kk * 32;
                ldsm4(bh[j], bd + OFF_BH);
                ldsm4(bl[j], bd + OFF_BL);
            }
#pragma unroll
            for (int mi = 0; mi < 2; ++mi)
#pragma unroll
                for (int j = 0; j < 4; ++j) {
                    mma16816(c[mi][2*j],   ah[mi], bh[j][0], bh[j][1]);
                    mma16816(c[mi][2*j+1], ah[mi], bh[j][2], bh[j][3]);
                    mma16816(c[mi][2*j],   ah[mi], bl[j][0], bl[j][1]);
                    mma16816(c[mi][2*j+1], ah[mi], bl[j][2], bl[j][3]);
                    mma16816(c[mi][2*j],   al[mi], bh[j][0], bh[j][1]);
                    mma16816(c[mi][2*j+1], al[mi], bh[j][2], bh[j][3]);
                }
        }
        __syncthreads();
    }
#pragma unroll
    for (int mi = 0; mi < 2; ++mi) {
        int gr = m0 + wm * 32 + mi * 16 + (lane >> 2);
#pragma unroll
        for (int ni = 0; ni < 8; ++ni) {
            int gc = n0 + wn * 64 + ni * 8 + (lane & 3) * 2;
            float2 bv = *(const float2*)&bias[gc];
            float* cc = c[mi][ni];
            *(float2*)&g_gx[(size_t)gr * G_ + gc] =
                make_float2(cc[0] + bv.x, cc[1] + bv.y);
            *(float2*)&g_gx[(size_t)(gr + 8) * G_ + gc] =
                make_float2(cc[2] + bv.x, cc[3] + bv.y);
        }
    }
}

// ---------------- persistent LSTM recurrence (R13, 4-chunk, fewer syncs) ------
__device__ __forceinline__ float sigf(float x) { return 1.0f / (1.0f + __expf(-x)); }

__device__ __forceinline__ void grid_bar(int bid, unsigned wantc) {
    __syncthreads();
    if (threadIdx.x < 8) {
        if (threadIdx.x == 0)
            asm volatile("red.release.gpu.global.add.u32 [%0], 1;"
                         :: "l"(&g_bars[(bid & 7) * 32]) : "memory");
        unsigned v;
        do {
            asm volatile("ld.acquire.gpu.global.u32 %0, [%1];"
                         : "=r"(v) : "l"(&g_bars[threadIdx.x * 32]));
        } while (v < wantc);
    }
    __syncthreads();
}

// SMEM byte offsets — 4 chunks of 256 k
#define WSTR 1032
#define OFF_WHI 0
#define OFF_WLO (32 * WSTR * 2)                // 66048
#define OFF_HS  (2 * 32 * WSTR * 2)            // 132096
#define HSTR 264
#define HS_HILO (32 * HSTR * 2)                // 16896
#define HS_BUF  (2 * HS_HILO)                  // 33792
#define OFF_RED (OFF_HS + 2 * HS_BUF)          // 199680
#define OFF_GS  (OFF_RED + 16 * 32 * 16 * 4 / 2)  // 16 slots of [32][16]? see note
#define REC_RED_BYTES (16 * 32 * 16 * 4)       // 32768
#undef OFF_GS
#define OFF_GS  (OFF_RED + REC_RED_BYTES)      // 232448 -> too big; shrink red below
// red only needs 16 slots x 32 x 16 f32 = 32KB; total would be 232KB > 227KB.
// Use red overlay INSIDE the h-staging area (free after mma of last chunk):
//   red at OFF_HS (h buffers fully consumed by then; barrier before next staging)
#undef OFF_RED
#define OFF_RED OFF_HS
#undef OFF_GS
#define OFF_GS  (OFF_HS + 2 * HS_BUF)          // 199680
#define OFF_LEN (OFF_GS + 32 * 36 * 4)         // 204288
#define REC_SMEM (OFF_LEN + 128)               // 204416

__global__ __launch_bounds__(512, 1) void lstm_rec(
    const float* __restrict__ whh, const void* __restrict__ len_raw,
    float* __restrict__ outp, float* __restrict__ cdst, float* __restrict__ hdst)
{
    extern __shared__ char sm[];
    const unsigned sbase = (unsigned)__cvta_generic_to_shared(sm);
    float* red = (float*)(sm + OFF_RED);       // overlays h buffers post-mma
    float* g_s = (float*)(sm + OFF_GS);
    int* len_s = (int*)(sm + OFF_LEN);

    const int tid = threadIdx.x, lane = tid & 31, wid = tid >> 5;
    const int bid = blockIdx.x;
    const int j0 = bid * 8;

    if (tid == 0) {
        const int* L = (const int*)len_raw;
        bool is64 = true;
        for (int i = 1; i < 32; i += 2) if (L[i] != 0) { is64 = false; break; }
        for (int b = 0; b < 32; ++b) len_s[b] = is64 ? L[2 * b] : L[b];
    }

    // stage + split W_hh slice (16 warps: 64 elems per thread)
    {
        const int r = tid & 31;
        const int grow = (r >> 3) * 1024 + j0 + (r & 7);
        const int k0 = (tid >> 5) * 64;
        const float* src = &whh[(size_t)grow * H_ + k0];
        __nv_bfloat162* whi = (__nv_bfloat162*)(sm + OFF_WHI);
        __nv_bfloat162* wlo = (__nv_bfloat162*)(sm + OFF_WLO);
#pragma unroll
        for (int kk = 0; kk < 64; kk += 4) {
            float4 v = *(const float4*)&src[kk];
            __nv_bfloat16 h0 = __float2bfloat16(v.x), h1 = __float2bfloat16(v.y);
            __nv_bfloat16 h2 = __float2bfloat16(v.z), h3 = __float2bfloat16(v.w);
            int e = r * WSTR + k0 + kk;
            whi[e / 2]     = __nv_bfloat162(h0, h1);
            whi[e / 2 + 1] = __nv_bfloat162(h2, h3);
            wlo[e / 2]     = __nv_bfloat162(__float2bfloat16(v.x - __bfloat162float(h0)),
                                            __float2bfloat16(v.y - __bfloat162float(h1)));
            wlo[e / 2 + 1] = __nv_bfloat162(__float2bfloat16(v.z - __bfloat162float(h2)),
                                            __float2bfloat16(v.w - __bfloat162float(h3)));
        }
    }

    // warp roles: kw = k-slice (8), nh = n-half (2)
    const int kw = wid >> 1, nh = wid & 1;
    const unsigned a_off = ((lane & 7) + (lane & 8)) * (WSTR * 2) + ((lane >> 4) * 8) * 2;
    const unsigned b_off = ((nh * 16 + (lane & 7) + (lane >> 4) * 8) * HSTR
                            + ((lane >> 3) & 1) * 8) * 2;

    // h staging: 512 threads, 2 uint4 x 2 sub-blocks = 32 elems each per 256-k chunk
    const int shl = tid >> 8, srem = tid & 255;
    const int sb = srem >> 3, sk = (srem & 7) * 16;
    const unsigned s_dst = OFF_HS + shl * HS_HILO + (sb * HSTR + sk) * 2;

    // reduce / gx map
    const int rm = tid >> 4, rn2 = (tid & 15) * 2;
    const int rslot_nh = rn2 >> 4, rcol = rn2 & 15;
    const size_t ocol = (size_t)(rm >> 3) * 1024 + j0 + (rm & 7);

    // update map
    const int ju = tid & 7, bu = tid >> 3;
    float c_reg = 0.f, h_reg = 0.f;
    if (tid < 256) {
        g_hb[0][0][bu * H_ + j0 + ju] = __float2bfloat16(0.f);
        g_hb[0][1][bu * H_ + j0 + ju] = __float2bfloat16(0.f);
    }

    unsigned wantc = 16;
    grid_bar(bid, wantc);

    for (int t = 0; t < T_; ++t) {
        float gx0 = __ldg(&g_gx[((size_t)rn2 * T_ + t) * G_ + ocol]);
        float gx1 = __ldg(&g_gx[((size_t)(rn2 + 1) * T_ + t) * G_ + ocol]);

        const __nv_bfloat16* hsrc = g_hb[t & 1][shl];
        // prologue: stage chunk 0 (two 16-elem groups: sk and sk+128)
        uint4 n0a = __ldcg((const uint4*)&hsrc[(size_t)sb * H_ + sk]);
        uint4 n0b = __ldcg((const uint4*)&hsrc[(size_t)sb * H_ + sk] + 1);
        uint4 n1a = __ldcg((const uint4*)&hsrc[(size_t)sb * H_ + sk + 128]);
        uint4 n1b = __ldcg((const uint4*)&hsrc[(size_t)sb * H_ + sk + 128] + 1);
        *(uint4*)(sm + s_dst)            = n0a;
        *(uint4*)(sm + s_dst + 16)       = n0b;
        *(uint4*)(sm + s_dst + 256)      = n1a;
        *(uint4*)(sm + s_dst + 256 + 16) = n1b;
        __syncthreads();

        float c[2][2][4];
#pragma unroll
        for (int mi = 0; mi < 2; ++mi)
#pragma unroll
            for (int nj = 0; nj < 2; ++nj)
#pragma unroll
                for (int q = 0; q < 4; ++q) c[mi][nj][q] = 0.f;

        for (int kc = 0; kc < 4; ++kc) {
            if (kc < 3) {
                size_t base = (size_t)sb * H_ + (kc + 1) * 256 + sk;
                n0a = __ldcg((const uint4*)&hsrc[base]);
                n0b = __ldcg((const uint4*)&hsrc[base] + 1);
                n1a = __ldcg((const uint4*)&hsrc[base + 128]);
                n1b = __ldcg((const uint4*)&hsrc[base + 128] + 1);
            }
            const unsigned hb_s = sbase + OFF_HS + (kc & 1) * HS_BUF;
#pragma unroll
            for (int ks = 0; ks < 2; ++ks) {
                const int kloc = kw * 32 + ks * 16;
                const int kg = kc * 256 + kloc;
                unsigned ah[2][4], al[2][4], bh[4], bl[4];
                unsigned bd = hb_s + b_off + kloc * 2;
                ldsm4(bh, bd);
                ldsm4(bl, bd + HS_HILO);
#pragma unroll
                for (int mi = 0; mi < 2; ++mi) {
                    unsigned ad = sbase + a_off + (mi * 16 * WSTR + kg) * 2;
                    ldsm4(ah[mi], ad + OFF_WHI);
                    ldsm4(al[mi], ad + OFF_WLO);
                }
#pragma unroll
                for (int mi = 0; mi < 2; ++mi)
#pragma unroll
                    for (int nj = 0; nj < 2; ++nj) {
                        mma16816(c[mi][nj], ah[mi], bh[2*nj], bh[2*nj+1]);
                        mma16816(c[mi][nj], ah[mi], bl[2*nj], bl[2*nj+1]);
                        mma16816(c[mi][nj], al[mi], bh[2*nj], bh[2*nj+1]);
                    }
            }
            if (kc < 3) {
                const unsigned nb_s = s_dst + ((kc + 1) & 1) * HS_BUF;
                *(uint4*)(sm + nb_s)            = n0a;
                *(uint4*)(sm + nb_s + 16)       = n0b;
                *(uint4*)(sm + nb_s + 256)      = n1a;
                *(uint4*)(sm + nb_s + 256 + 16) = n1b;
                __syncthreads();
            }
        }
        __syncthreads();   // all mma done; h buffers free -> red overlay safe

        // partials: slot = kw*2+nh (overlays h staging area)
#pragma unroll
        for (int mi = 0; mi < 2; ++mi)
#pragma unroll
            for (int nj = 0; nj < 2; ++nj) {
                int m = mi * 16 + (lane >> 2);
                int nl = nj * 8 + (lane & 3) * 2;
                float* rb = &red[((kw * 2 + nh) * 32) * 16];
                *(float2*)&rb[m * 16 + nl]       = make_float2(c[mi][nj][0], c[mi][nj][1]);
                *(float2*)&rb[(m + 8) * 16 + nl] = make_float2(c[mi][nj][2], c[mi][nj][3]);
            }
        __syncthreads();

        // reduce over 8 kw-slots + gx
        {
            float s0 = gx0, s1 = gx1;
#pragma unroll
            for (int s = 0; s < 8; ++s) {
                float2 p = *(float2*)&red[((s * 2 + rslot_nh) * 32 + rm) * 16 + rcol];
                s0 += p.x; s1 += p.y;
            }
            g_s[rm * 36 + rn2]     = s0;
            g_s[rm * 36 + rn2 + 1] = s1;
        }
        __syncthreads();

        // pointwise update (fp32 state), threads 0..255
        if (tid < 256) {
            float fg = sigf(g_s[(0 * 8 + ju) * 36 + bu]);
            float ig = sigf(g_s[(1 * 8 + ju) * 36 + bu]);
            float og = sigf(g_s[(2 * 8 + ju) * 36 + bu]);
            float cg = tanhf(g_s[(3 * 8 + ju) * 36 + bu]);
            float cn = fg * c_reg + ig * cg;
            float hn = og * tanhf(cn);
            if (t < len_s[bu]) { c_reg = cn; h_reg = hn; }
            __nv_bfloat16 hh = __float2bfloat16(h_reg);
            __nv_bfloat16 hl = __float2bfloat16(h_reg - __bfloat162float(hh));
            int nbuf = (t & 1) ^ 1;
            g_hb[nbuf][0][bu * H_ + j0 + ju] = hh;
            g_hb[nbuf][1][bu * H_ + j0 + ju] = hl;
            outp[((size_t)bu * T_ + t) * H_ + (j0 + ju)] = h_reg;
        }

        wantc += 16;
        grid_bar(bid, wantc);
    }
    if (tid < 256) {
        cdst[(size_t)bu * H_ + j0 + ju] = c_reg;
        hdst[(size_t)bu * H_ + j0 + ju] = h_reg;
    }
}

extern "C" void kernel_launch(void* const* d_in, const int* in_sizes, int n_in,
                              void* d_out, int out_size)
{
    const float* x    = (const float*)d_in[0];
    const void*  len  = d_in[1];
    const float* wih0 = (const float*)d_in[2];
    const float* whh0 = (const float*)d_in[3];
    const float* b0   = (const float*)d_in[4];
    const float* wih1 = (const float*)d_in[5];
    const float* whh1 = (const float*)d_in[6];
    const float* b1   = (const float*)d_in[7];
    float* out = (float*)d_out;

    void *bar_p, *out0_p, *ahi_p, *alo_p, *whi_p, *wlo_p;
    cudaGetSymbolAddress(&bar_p, g_bars);
    cudaGetSymbolAddress(&out0_p, g_out0);
    cudaGetSymbolAddress(&ahi_p, g_Ahi);
    cudaGetSymbolAddress(&alo_p, g_Alo);
    cudaGetSymbolAddress(&whi_p, g_Whi);
    cudaGetSymbolAddress(&wlo_p, g_Wlo);
    float* out0 = (float*)out0_p;
    __nv_bfloat16* Ahi = (__nv_bfloat16*)ahi_p;
    __nv_bfloat16* Alo = (__nv_bfloat16*)alo_p;
    __nv_bfloat16* Whi = (__nv_bfloat16*)whi_p;
    __nv_bfloat16* Wlo = (__nv_bfloat16*)wlo_p;

    cudaFuncSetAttribute(lstm_rec, cudaFuncAttributeMaxDynamicSharedMemorySize, REC_SMEM);
    cudaFuncSetAttribute(tc_gemm, cudaFuncAttributeMaxDynamicSharedMemorySize, TC_SMEM);

    const size_t O1 = (size_t)B_ * T_ * H_;
    float* c0dst = out + O1;
    float* c1dst = out + O1 + (size_t)B_ * H_;
    float* h0dst = out + O1 + 2 * (size_t)B_ * H_;
    float* h1dst = out + O1 + 3 * (size_t)B_ * H_;

    const int nA4 = (B_ * T_ * H_) / 4;
    const int nW4 = (G_ * H_) / 4;
    dim3 gg(G_ / 128, (B_ * T_) / 128);

    conv_split<<<nW4 / 256, 256>>>(wih0, Whi, Wlo, nW4);
    conv_split<<<nA4 / 256, 256>>>(x, Ahi, Alo, nA4);
    tc_gemm<<<gg, 256, TC_SMEM>>>(Ahi, Alo, Whi, Wlo, b0);
    cudaMemsetAsync(bar_p, 0, 8 * 32 * sizeof(unsigned), 0);
    lstm_rec<<<NB, 512, REC_SMEM>>>(whh0, len, out0, c0dst, h0dst);

    conv_split<<<nW4 / 256, 256>>>(wih1, Whi, Wlo, nW4);
    conv_split<<<nA4 / 256, 256>>>(out0, Ahi, Alo, nA4);
    tc_gemm<<<gg, 256, TC_SMEM>>>(Ahi, Alo, Whi, Wlo, b1);
    cudaMemsetAsync(bar_p, 0, 8 * 32 * sizeof(unsigned), 0);
    lstm_rec<<<NB, 512, REC_SMEM>>>(whh1, len, out, c1dst, h1dst);
}

// round 17
// speedup vs baseline: 1.2780x; 1.1539x over previous
#include <cuda_runtime.h>
#include <cuda_bf16.h>
#include <cstddef>

#define B_ 32
#define T_ 512
#define H_ 1024
#define G_ 4096
#define NB 128

__device__ float g_gx[(size_t)B_ * T_ * G_];
__device__ float g_out0[(size_t)B_ * T_ * H_];
__device__ __nv_bfloat16 g_hb[2][2][(size_t)B_ * H_];
__device__ unsigned g_bars[8 * 32];
__device__ __nv_bfloat16 g_Ahi[(size_t)B_ * T_ * H_];
__device__ __nv_bfloat16 g_Alo[(size_t)B_ * T_ * H_];
__device__ __nv_bfloat16 g_Whi[(size_t)G_ * H_];
__device__ __nv_bfloat16 g_Wlo[(size_t)G_ * H_];

__global__ __launch_bounds__(256) void conv_split(
    const float* __restrict__ s, __nv_bfloat16* __restrict__ hi,
    __nv_bfloat16* __restrict__ lo, int n4)
{
    int i = blockIdx.x * 256 + threadIdx.x;
    if (i >= n4) return;
    float4 v = ((const float4*)s)[i];
    __nv_bfloat16 h0 = __float2bfloat16(v.x), h1 = __float2bfloat16(v.y);
    __nv_bfloat16 h2 = __float2bfloat16(v.z), h3 = __float2bfloat16(v.w);
    __nv_bfloat16 l0 = __float2bfloat16(v.x - __bfloat162float(h0));
    __nv_bfloat16 l1 = __float2bfloat16(v.y - __bfloat162float(h1));
    __nv_bfloat16 l2 = __float2bfloat16(v.z - __bfloat162float(h2));
    __nv_bfloat16 l3 = __float2bfloat16(v.w - __bfloat162float(h3));
    ((__nv_bfloat162*)hi)[i * 2]     = __nv_bfloat162(h0, h1);
    ((__nv_bfloat162*)hi)[i * 2 + 1] = __nv_bfloat162(h2, h3);
    ((__nv_bfloat162*)lo)[i * 2]     = __nv_bfloat162(l0, l1);
    ((__nv_bfloat162*)lo)[i * 2 + 1] = __nv_bfloat162(l2, l3);
}

__device__ __forceinline__ void ldsm4(unsigned* r, unsigned a) {
    asm volatile("ldmatrix.sync.aligned.m8n8.x4.shared.b16 {%0,%1,%2,%3}, [%4];"
                 : "=r"(r[0]), "=r"(r[1]), "=r"(r[2]), "=r"(r[3]) : "r"(a));
}
__device__ __forceinline__ void mma16816(float* c, const unsigned* a,
                                         unsigned b0, unsigned b1) {
    asm volatile(
        "mma.sync.aligned.m16n8k16.row.col.f32.bf16.bf16.f32 "
        "{%0,%1,%2,%3}, {%4,%5,%6,%7}, {%8,%9}, {%0,%1,%2,%3};"
        : "+f"(c[0]), "+f"(c[1]), "+f"(c[2]), "+f"(c[3])
        : "r"(a[0]), "r"(a[1]), "r"(a[2]), "r"(a[3]), "r"(b0), "r"(b1));
}
__device__ __forceinline__ void cpa(unsigned s, const void* g) {
    asm volatile("cp.async.cg.shared.global [%0], [%1], 16;" :: "r"(s), "l"(g));
}

// ---------------- tensor-core GEMM (unchanged) --------------------------------
#define SR 40
#define BUFB (128 * SR * 2)
#define OFF_AH 0
#define OFF_AL (2 * BUFB)
#define OFF_BH (4 * BUFB)
#define OFF_BL (6 * BUFB)
#define TC_SMEM (8 * BUFB)

__global__ __launch_bounds__(256, 1) void tc_gemm(
    const __nv_bfloat16* __restrict__ Ahi, const __nv_bfloat16* __restrict__ Alo,
    const __nv_bfloat16* __restrict__ Whi, const __nv_bfloat16* __restrict__ Wlo,
    const float* __restrict__ bias)
{
    extern __shared__ char sm[];
    const unsigned sbase = (unsigned)__cvta_generic_to_shared(sm);
    const int tid = threadIdx.x, lane = tid & 31, wid = tid >> 5;
    const int wm = wid & 3, wn = wid >> 2;
    const int m0 = blockIdx.y * 128, n0 = blockIdx.x * 128;

    int frow[2], fch[2];
    unsigned sA[2];
#pragma unroll
    for (int u = 0; u < 2; ++u) {
        int id = tid + 256 * u;
        frow[u] = id >> 2; fch[u] = (id & 3) * 8;
        sA[u] = (frow[u] * SR + fch[u]) * 2;
    }
    const int arow = wm * 32 + (lane & 7) + (lane & 8);
    const unsigned a_base = (arow * SR + (lane >> 4) * 8) * 2;
    const int brow = wn * 64 + (lane & 7) + (lane >> 4) * 8;
    const unsigned b_base = (brow * SR + ((lane >> 3) & 1) * 8) * 2;

    float c[2][8][4];
#pragma unroll
    for (int i = 0; i < 2; ++i)
#pragma unroll
        for (int j = 0; j < 8; ++j)
#pragma unroll
            for (int q = 0; q < 4; ++q) c[i][j][q] = 0.f;

#pragma unroll
    for (int u = 0; u < 2; ++u) {
        size_t ga = (size_t)(m0 + frow[u]) * H_ + fch[u];
        size_t gb = (size_t)(n0 + frow[u]) * H_ + fch[u];
        cpa(sbase + OFF_AH + sA[u], &Ahi[ga]);
        cpa(sbase + OFF_AL + sA[u], &Alo[ga]);
        cpa(sbase + OFF_BH + sA[u], &Whi[gb]);
        cpa(sbase + OFF_BL + sA[u], &Wlo[gb]);
    }
    asm volatile("cp.async.commit_group;");

    for (int s = 0; s < 32; ++s) {
        asm volatile("cp.async.wait_group 0;");
        __syncthreads();
        if (s + 1 < 32) {
            int k0 = (s + 1) * 32, bf = (s + 1) & 1;
#pragma unroll
            for (int u = 0; u < 2; ++u) {
                size_t ga = (size_t)(m0 + frow[u]) * H_ + k0 + fch[u];
                size_t gb = (size_t)(n0 + frow[u]) * H_ + k0 + fch[u];
                cpa(sbase + OFF_AH + bf * BUFB + sA[u], &Ahi[ga]);
                cpa(sbase + OFF_AL + bf * BUFB + sA[u], &Alo[ga]);
                cpa(sbase + OFF_BH + bf * BUFB + sA[u], &Whi[gb]);
                cpa(sbase + OFF_BL + bf * BUFB + sA[u], &Wlo[gb]);
            }
            asm volatile("cp.async.commit_group;");
        }
        const unsigned bo = (s & 1) * BUFB;
#pragma unroll
        for (int kk = 0; kk < 2; ++kk) {
            unsigned ah[2][4], al[2][4], bh[4][4], bl[4][4];
#pragma unroll
            for (int mi = 0; mi < 2; ++mi) {
                unsigned ad = sbase + bo + a_base + mi * (16 * SR * 2) + kk * 32;
                ldsm4(ah[mi], ad + OFF_AH);
                ldsm4(al[mi], ad + OFF_AL);
            }
#pragma unroll
            for (int j = 0; j < 4; ++j) {
                unsigned bd = sbase + bo + b_base + j * (16 * SR * 2) + kk * 32;
                ldsm4(bh[j], bd + OFF_BH);
                ldsm4(bl[j], bd + OFF_BL);
            }
#pragma unroll
            for (int mi = 0; mi < 2; ++mi)
#pragma unroll
                for (int j = 0; j < 4; ++j) {
                    mma16816(c[mi][2*j],   ah[mi], bh[j][0], bh[j][1]);
                    mma16816(c[mi][2*j+1], ah[mi], bh[j][2], bh[j][3]);
                    mma16816(c[mi][2*j],   ah[mi], bl[j][0], bl[j][1]);
                    mma16816(c[mi][2*j+1], ah[mi], bl[j][2], bl[j][3]);
                    mma16816(c[mi][2*j],   al[mi], bh[j][0], bh[j][1]);
                    mma16816(c[mi][2*j+1], al[mi], bh[j][2], bh[j][3]);
                }
        }
        __syncthreads();
    }
#pragma unroll
    for (int mi = 0; mi < 2; ++mi) {
        int gr = m0 + wm * 32 + mi * 16 + (lane >> 2);
#pragma unroll
        for (int ni = 0; ni < 8; ++ni) {
            int gc = n0 + wn * 64 + ni * 8 + (lane & 3) * 2;
            float2 bv = *(const float2*)&bias[gc];
            float* cc = c[mi][ni];
            *(float2*)&g_gx[(size_t)gr * G_ + gc] =
                make_float2(cc[0] + bv.x, cc[1] + bv.y);
            *(float2*)&g_gx[(size_t)(gr + 8) * G_ + gc] =
                make_float2(cc[2] + bv.x, cc[3] + bv.y);
        }
    }
}

// ---------------- persistent LSTM recurrence (R16 + LDGSTS + sync cut) --------
__device__ __forceinline__ float sigf(float x) { return 1.0f / (1.0f + __expf(-x)); }

__device__ __forceinline__ void grid_bar(int bid, unsigned wantc) {
    __syncthreads();
    if (threadIdx.x < 8) {
        if (threadIdx.x == 0)
            asm volatile("red.release.gpu.global.add.u32 [%0], 1;"
                         :: "l"(&g_bars[(bid & 7) * 32]) : "memory");
        unsigned v;
        do {
            asm volatile("ld.acquire.gpu.global.u32 %0, [%1];"
                         : "=r"(v) : "l"(&g_bars[threadIdx.x * 32]));
        } while (v < wantc);
    }
    __syncthreads();
}

// SMEM byte offsets — 4 chunks of 256 k; red overlays h buffer 0
#define WSTR 1032
#define OFF_WHI 0
#define OFF_WLO (32 * WSTR * 2)                // 66048
#define OFF_HS  (2 * 32 * WSTR * 2)            // 132096
#define HSTR 264
#define HS_HILO (32 * HSTR * 2)                // 16896
#define HS_BUF  (2 * HS_HILO)                  // 33792
#define OFF_RED OFF_HS
#define OFF_GS  (OFF_HS + 2 * HS_BUF)          // 199680
#define OFF_LEN (OFF_GS + 32 * 36 * 4)         // 204288
#define REC_SMEM (OFF_LEN + 128)               // 204416

__global__ __launch_bounds__(512, 1) void lstm_rec(
    const float* __restrict__ whh, const void* __restrict__ len_raw,
    float* __restrict__ outp, float* __restrict__ cdst, float* __restrict__ hdst)
{
    extern __shared__ char sm[];
    const unsigned sbase = (unsigned)__cvta_generic_to_shared(sm);
    float* red = (float*)(sm + OFF_RED);
    float* g_s = (float*)(sm + OFF_GS);
    int* len_s = (int*)(sm + OFF_LEN);

    const int tid = threadIdx.x, lane = tid & 31, wid = tid >> 5;
    const int bid = blockIdx.x;
    const int j0 = bid * 8;

    if (tid == 0) {
        const int* L = (const int*)len_raw;
        bool is64 = true;
        for (int i = 1; i < 32; i += 2) if (L[i] != 0) { is64 = false; break; }
        for (int b = 0; b < 32; ++b) len_s[b] = is64 ? L[2 * b] : L[b];
    }

    // stage + split W_hh slice (16 warps: 64 elems per thread)
    {
        const int r = tid & 31;
        const int grow = (r >> 3) * 1024 + j0 + (r & 7);
        const int k0 = (tid >> 5) * 64;
        const float* src = &whh[(size_t)grow * H_ + k0];
        __nv_bfloat162* whi = (__nv_bfloat162*)(sm + OFF_WHI);
        __nv_bfloat162* wlo = (__nv_bfloat162*)(sm + OFF_WLO);
#pragma unroll
        for (int kk = 0; kk < 64; kk += 4) {
            float4 v = *(const float4*)&src[kk];
            __nv_bfloat16 h0 = __float2bfloat16(v.x), h1 = __float2bfloat16(v.y);
            __nv_bfloat16 h2 = __float2bfloat16(v.z), h3 = __float2bfloat16(v.w);
            int e = r * WSTR + k0 + kk;
            whi[e / 2]     = __nv_bfloat162(h0, h1);
            whi[e / 2 + 1] = __nv_bfloat162(h2, h3);
            wlo[e / 2]     = __nv_bfloat162(__float2bfloat16(v.x - __bfloat162float(h0)),
                                            __float2bfloat16(v.y - __bfloat162float(h1)));
            wlo[e / 2 + 1] = __nv_bfloat162(__float2bfloat16(v.z - __bfloat162float(h2)),
                                            __float2bfloat16(v.w - __bfloat162float(h3)));
        }
    }

    // warp roles: kw = k-slice (8), nh = n-half (2)
    const int kw = wid >> 1, nh = wid & 1;
    const unsigned a_off = ((lane & 7) + (lane & 8)) * (WSTR * 2) + ((lane >> 4) * 8) * 2;
    const unsigned b_off = ((nh * 16 + (lane & 7) + (lane >> 4) * 8) * HSTR
                            + ((lane >> 3) & 1) * 8) * 2;

    // h staging: 512 threads, 4 x 16B cp.async each per 256-k chunk
    const int shl = tid >> 8, srem = tid & 255;
    const int sb = srem >> 3, sk = (srem & 7) * 16;
    const unsigned s_dst = sbase + OFF_HS + shl * HS_HILO + (sb * HSTR + sk) * 2;

    // reduce / gx map
    const int rm = tid >> 4, rn2 = (tid & 15) * 2;
    const int rslot_nh = rn2 >> 4, rcol = rn2 & 15;
    const size_t ocol = (size_t)(rm >> 3) * 1024 + j0 + (rm & 7);

    // update map
    const int ju = tid & 7, bu = tid >> 3;
    float c_reg = 0.f, h_reg = 0.f;
    if (tid < 256) {
        g_hb[0][0][bu * H_ + j0 + ju] = __float2bfloat16(0.f);
        g_hb[0][1][bu * H_ + j0 + ju] = __float2bfloat16(0.f);
    }

    unsigned wantc = 16;
    grid_bar(bid, wantc);

    for (int t = 0; t < T_; ++t) {
        float gx0 = __ldg(&g_gx[((size_t)rn2 * T_ + t) * G_ + ocol]);
        float gx1 = __ldg(&g_gx[((size_t)(rn2 + 1) * T_ + t) * G_ + ocol]);

        const __nv_bfloat16* hsrc = g_hb[t & 1][shl];
        // prologue: issue chunk 0 via cp.async
        {
            const __nv_bfloat16* b0p = &hsrc[(size_t)sb * H_ + sk];
            cpa(s_dst,            b0p);
            cpa(s_dst + 16,       b0p + 8);
            cpa(s_dst + 256,      b0p + 128);
            cpa(s_dst + 256 + 16, b0p + 136);
            asm volatile("cp.async.commit_group;");
        }

        float c[2][2][4];
#pragma unroll
        for (int mi = 0; mi < 2; ++mi)
#pragma unroll
            for (int nj = 0; nj < 2; ++nj)
#pragma unroll
                for (int q = 0; q < 4; ++q) c[mi][nj][q] = 0.f;

        for (int kc = 0; kc < 4; ++kc) {
            asm volatile("cp.async.wait_group 0;");
            __syncthreads();                       // chunk kc visible; prev readers done
            if (kc < 3) {
                const __nv_bfloat16* bp = &hsrc[(size_t)sb * H_ + (kc + 1) * 256 + sk];
                const unsigned nb_s = s_dst + ((kc + 1) & 1) * HS_BUF;
                cpa(nb_s,            bp);
                cpa(nb_s + 16,       bp + 8);
                cpa(nb_s + 256,      bp + 128);
                cpa(nb_s + 256 + 16, bp + 136);
                asm volatile("cp.async.commit_group;");
            }
            const unsigned hb_s = sbase + OFF_HS + (kc & 1) * HS_BUF;
#pragma unroll
            for (int ks = 0; ks < 2; ++ks) {
                const int kloc = kw * 32 + ks * 16;
                const int kg = kc * 256 + kloc;
                unsigned ah[2][4], al[2][4], bh[4], bl[4];
                unsigned bd = hb_s + b_off + kloc * 2;
                ldsm4(bh, bd);
                ldsm4(bl, bd + HS_HILO);
#pragma unroll
                for (int mi = 0; mi < 2; ++mi) {
                    unsigned ad = sbase + a_off + (mi * 16 * WSTR + kg) * 2;
                    ldsm4(ah[mi], ad + OFF_WHI);
                    ldsm4(al[mi], ad + OFF_WLO);
                }
#pragma unroll
                for (int mi = 0; mi < 2; ++mi)
#pragma unroll
                    for (int nj = 0; nj < 2; ++nj) {
                        mma16816(c[mi][nj], ah[mi], bh[2*nj], bh[2*nj+1]);
                        mma16816(c[mi][nj], ah[mi], bl[2*nj], bl[2*nj+1]);
                        mma16816(c[mi][nj], al[mi], bh[2*nj], bh[2*nj+1]);
                    }
            }
        }
        // no sync needed: partials overlay buffer 0; chunk-3 mma reads buffer 1

        // partials: slot = kw*2+nh (overlays h buffer 0)
#pragma unroll
        for (int mi = 0; mi < 2; ++mi)
#pragma unroll
            for (int nj = 0; nj < 2; ++nj) {
                int m = mi * 16 + (lane >> 2);
                int nl = nj * 8 + (lane & 3) * 2;
                float* rb = &red[((kw * 2 + nh) * 32) * 16];
                *(float2*)&rb[m * 16 + nl]       = make_float2(c[mi][nj][0], c[mi][nj][1]);
                *(float2*)&rb[(m + 8) * 16 + nl] = make_float2(c[mi][nj][2], c[mi][nj][3]);
            }
        __syncthreads();

        // reduce over 8 kw-slots + gx
        {
            float s0 = gx0, s1 = gx1;
#pragma unroll
            for (int s = 0; s < 8; ++s) {
                float2 p = *(float2*)&red[((s * 2 + rslot_nh) * 32 + rm) * 16 + rcol];
                s0 += p.x; s1 += p.y;
            }
            g_s[rm * 36 + rn2]     = s0;
            g_s[rm * 36 + rn2 + 1] = s1;
        }
        __syncthreads();

        // pointwise update (fp32 state), threads 0..255
        if (tid < 256) {
            float fg = sigf(g_s[(0 * 8 + ju) * 36 + bu]);
            float ig = sigf(g_s[(1 * 8 + ju) * 36 + bu]);
            float og = sigf(g_s[(2 * 8 + ju) * 36 + bu]);
            float cg = tanhf(g_s[(3 * 8 + ju) * 36 + bu]);
            float cn = fg * c_reg + ig * cg;
            float hn = og * tanhf(cn);
            if (t < len_s[bu]) { c_reg = cn; h_reg = hn; }
            __nv_bfloat16 hh = __float2bfloat16(h_reg);
            __nv_bfloat16 hl = __float2bfloat16(h_reg - __bfloat162float(hh));
            int nbuf = (t & 1) ^ 1;
            g_hb[nbuf][0][bu * H_ + j0 + ju] = hh;
            g_hb[nbuf][1][bu * H_ + j0 + ju] = hl;
            outp[((size_t)bu * T_ + t) * H_ + (j0 + ju)] = h_reg;
        }

        wantc += 16;
        grid_bar(bid, wantc);
    }
    if (tid < 256) {
        cdst[(size_t)bu * H_ + j0 + ju] = c_reg;
        hdst[(size_t)bu * H_ + j0 + ju] = h_reg;
    }
}

extern "C" void kernel_launch(void* const* d_in, const int* in_sizes, int n_in,
                              void* d_out, int out_size)
{
    const float* x    = (const float*)d_in[0];
    const void*  len  = d_in[1];
    const float* wih0 = (const float*)d_in[2];
    const float* whh0 = (const float*)d_in[3];
    const float* b0   = (const float*)d_in[4];
    const float* wih1 = (const float*)d_in[5];
    const float* whh1 = (const float*)d_in[6];
    const float* b1   = (const float*)d_in[7];
    float* out = (float*)d_out;

    void *bar_p, *out0_p, *ahi_p, *alo_p, *whi_p, *wlo_p;
    cudaGetSymbolAddress(&bar_p, g_bars);
    cudaGetSymbolAddress(&out0_p, g_out0);
    cudaGetSymbolAddress(&ahi_p, g_Ahi);
    cudaGetSymbolAddress(&alo_p, g_Alo);
    cudaGetSymbolAddress(&whi_p, g_Whi);
    cudaGetSymbolAddress(&wlo_p, g_Wlo);
    float* out0 = (float*)out0_p;
    __nv_bfloat16* Ahi = (__nv_bfloat16*)ahi_p;
    __nv_bfloat16* Alo = (__nv_bfloat16*)alo_p;
    __nv_bfloat16* Whi = (__nv_bfloat16*)whi_p;
    __nv_bfloat16* Wlo = (__nv_bfloat16*)wlo_p;

    cudaFuncSetAttribute(lstm_rec, cudaFuncAttributeMaxDynamicSharedMemorySize, REC_SMEM);
    cudaFuncSetAttribute(tc_gemm, cudaFuncAttributeMaxDynamicSharedMemorySize, TC_SMEM);

    const size_t O1 = (size_t)B_ * T_ * H_;
    float* c0dst = out + O1;
    float* c1dst = out + O1 + (size_t)B_ * H_;
    float* h0dst = out + O1 + 2 * (size_t)B_ * H_;
    float* h1dst = out + O1 + 3 * (size_t)B_ * H_;

    const int nA4 = (B_ * T_ * H_) / 4;
    const int nW4 = (G_ * H_) / 4;
    dim3 gg(G_ / 128, (B_ * T_) / 128);

    conv_split<<<nW4 / 256, 256>>>(wih0, Whi, Wlo, nW4);
    conv_split<<<nA4 / 256, 256>>>(x, Ahi, Alo, nA4);
    tc_gemm<<<gg, 256, TC_SMEM>>>(Ahi, Alo, Whi, Wlo, b0);
    cudaMemsetAsync(bar_p, 0, 8 * 32 * sizeof(unsigned), 0);
    lstm_rec<<<NB, 512, REC_SMEM>>>(whh0, len, out0, c0dst, h0dst);

    conv_split<<<nW4 / 256, 256>>>(wih1, Whi, Wlo, nW4);
    conv_split<<<nA4 / 256, 256>>>(out0, Ahi, Alo, nA4);
    tc_gemm<<<gg, 256, TC_SMEM>>>(Ahi, Alo, Whi, Wlo, b1);
    cudaMemsetAsync(bar_p, 0, 8 * 32 * sizeof(unsigned), 0);
    lstm_rec<<<NB, 512, REC_SMEM>>>(whh1, len, out, c1dst, h1dst);
}